// round 15
// baseline (speedup 1.0000x reference)
#include <cuda_runtime.h>
#include <cuda_bf16.h>
#include <math.h>

#define CROP 448
#define NR   56      // cells per side
#define NB   55      // blocks per side
#define B    48
#define IMG  512
#define TOP  32

#define TW   224     // kernel-1 tile width (columns per CTA)
#define SG1  232     // staged row width: TW + 8 (4 halo/pad each side)
#define NQ   58      // staged float4 quads per row

// Cell histogram scratch: [b][cell_r][cell_c][bin]
__device__ float g_hist[(size_t)B * NR * NR * 9];
// Per-cell sum of squares: [b][cell_r][cell_c]
__device__ float g_cellss[(size_t)B * NR * NR];

__device__ __forceinline__ float fsqrt_approx(float x) {
    float r;
    asm("sqrt.approx.f32 %0, %1;" : "=f"(r) : "f"(x));
    return r;
}
__device__ __forceinline__ float frcp_approx(float x) {
    float r;
    asm("rcp.approx.f32 %0, %1;" : "=f"(r) : "f"(x));
    return r;
}

// ---------------------------------------------------------------------------
// Kernel 1: gray -> sqrt -> gradients -> per-cell prefix histograms (+cell ss)
// grid: (2, NR, B) — two 224-column tiles per cell-row. 224-thread CTAs,
// 7 CTAs/SM: many small independent staging pipelines to hide DRAM latency.
// ---------------------------------------------------------------------------
__global__ __launch_bounds__(TW, 7) void hog_cells_kernel(
    const float* __restrict__ x, const float* __restrict__ coeffs,
    float* __restrict__ hist, float* __restrict__ cellss)
{
    __shared__ float sg[10][SG1];    // global col c at index c - c0 + 4

    const int tx = blockIdx.x;       // column tile 0..1
    const int cr = blockIdx.y;       // cell row 0..55
    const int b  = blockIdx.z;
    const int cl = threadIdx.x;      // local column 0..223
    const int c0 = tx * TW;
    const int r0 = cr * 8;

    const float c0f = coeffs[0], c1f = coeffs[1], c2f = coeffs[2];
    const float* base = x + (size_t)b * 3 * IMG * IMG;

    // Stage 10 rows x 58 quads of sqrt(gray). Row reflection at image
    // top/bottom; column reflection at image left/right handled by the
    // left/right clamped quads (col -1 := col 1, col 448 := col 446).
    for (int e = cl; e < 10 * NQ; e += TW) {
        int i  = e / NQ;
        int qg = e - i * NQ;
        int gcol = c0 - 4 + qg * 4;            // global crop col of quad start
        int r = r0 - 1 + i;
        if (r < 0) r = -r;                     // -1 -> 1
        if (r > CROP - 1) r = 2 * (CROP - 1) - r;

        int lcol = gcol;
        if (gcol < 0)   lcol = 0;              // tile 0, leftmost quad
        if (gcol > 444) lcol = 444;            // tile 1, rightmost quad (448)

        const float4* p = (const float4*)(base + (size_t)(r + TOP) * IMG + TOP + lcol);
        float4 a0 = p[0];
        float4 a1 = p[(IMG * IMG) / 4];
        float4 a2 = p[(2 * IMG * IMG) / 4];
        float4 g;
        g.x = fsqrt_approx(fmaf(c0f, a0.x, fmaf(c1f, a1.x, c2f * a2.x)));
        g.y = fsqrt_approx(fmaf(c0f, a0.y, fmaf(c1f, a1.y, c2f * a2.y)));
        g.z = fsqrt_approx(fmaf(c0f, a0.z, fmaf(c1f, a1.z, c2f * a2.z)));
        g.w = fsqrt_approx(fmaf(c0f, a0.w, fmaf(c1f, a1.w, c2f * a2.w)));

        if (gcol < 0) {
            *((float4*)&sg[i][0]) = g;         // cols 0..3 (positional garbage)
            sg[i][3] = g.y;                    // col -1 := col 1 (only idx read)
        } else if (gcol > 444) {
            sg[i][228] = g.z;                  // col 448 := col 446
        } else {
            *((float4*)&sg[i][gcol - c0 + 4]) = g;
        }
    }
    __syncthreads();

    // cot(20k degrees), k = 1..8
    const float KT[8] = { 2.7474774f,  1.1917536f,  0.57735027f,  0.17632698f,
                         -0.17632698f, -0.57735027f, -1.1917536f, -2.7474774f};
    const float INF = __int_as_float(0x7f800000);

    float vreg[10];
    #pragma unroll
    for (int i = 0; i < 10; i++) vreg[i] = sg[i][cl + 4];

    // Prefix histogram: H[k] = sum of mag over pixels with angle >= 20k.
    float H[9];
    #pragma unroll
    for (int k = 0; k < 9; k++) H[k] = 0.f;

    #pragma unroll
    for (int i = 0; i < 8; i++) {
        float gr = vreg[i + 2] - vreg[i];
        float gc = sg[i + 1][cl + 5] - sg[i + 1][cl + 3];

        float mag = fsqrt_approx(fmaf(gr, gr, gc * gc));

        // w = cot(angle) = gc/gr (period 180 => no half-plane fold).
        // gr==0 -> +inf -> bin 0, matching the reference's 180 % 180 = 0.
        float w = gc * frcp_approx(gr);
        if (gr == 0.f) w = INF;

        H[0] += mag;
        #pragma unroll
        for (int k = 0; k < 8; k++)
            if (w <= KT[k]) H[k + 1] += mag;
    }

    #pragma unroll
    for (int k = 0; k < 9; k++) {
        H[k] += __shfl_xor_sync(0xffffffffu, H[k], 1);
        H[k] += __shfl_xor_sync(0xffffffffu, H[k], 2);
        H[k] += __shfl_xor_sync(0xffffffffu, H[k], 4);
    }

    if ((cl & 7) == 0) {
        int cell = (c0 + cl) >> 3;    // 0..55
        size_t cidx = ((size_t)b * NR + cr) * NR + cell;
        float ss = 0.f;
        #pragma unroll
        for (int k = 0; k < 9; k++) {
            float hk = ((k < 8) ? (H[k] - H[k + 1]) : H[8]) * (1.0f / 64.0f);
            hist[cidx * 9 + k] = hk;
            ss += hk * hk;
        }
        cellss[cidx] = ss;
    }
}

// ---------------------------------------------------------------------------
// Kernel 2: L2-Hys block normalization. One CTA per (b, 2 block-rows),
// 512 threads = 16 warps: warps 0-7 handle row I0, warps 8-15 row I0+1
// IN PARALLEL (no serialization). Stages 3 hist rows once (756/row vs 1008).
// ---------------------------------------------------------------------------
#define K2T 512
#define NT2 28              // CTAs per image: ceil(55/2)
#define VSTRIDE 37          // padded per-block stride in vbuf

__global__ __launch_bounds__(K2T) void hog_blocks_kernel(
    const float* __restrict__ hist, const float* __restrict__ cellss,
    float* __restrict__ out)
{
    __shared__ float sh[3 * NR * 9];        // hist rows I0..I0+2 (1512)
    __shared__ float scs[3 * NR];           // cell ss rows (168)
    __shared__ float vbuf[2 * NB * VSTRIDE];// normalized blocks, 2 rows

    const int b  = blockIdx.x / NT2;
    const int t  = blockIdx.x % NT2;
    const int I0 = 2 * t;
    const int tid = threadIdx.x;

    const int nhr = (I0 == 54) ? 2 : 3;     // hist rows to stage
    const int nbr = (I0 == 54) ? 1 : 2;     // block rows produced

    // Stage hist rows as float4 (nhr*126 <= 378 <= 512: single pass).
    {
        const float4* src4 = (const float4*)(hist + ((size_t)b * NR + I0) * NR * 9);
        if (tid < nhr * 126) ((float4*)sh)[tid] = src4[tid];
        const float* cs = cellss + ((size_t)b * NR + I0) * NR;
        if (tid < nhr * NR) scs[tid] = cs[tid];
    }
    __syncthreads();

    const int w    = tid >> 5;
    const int lane = tid & 31;
    const int half = w >> 3;              // 0 or 1: which block row
    const int wl   = w & 7;
    const int g    = lane & 3;            // cell within block
    const int J    = wl + 8 * (lane >> 2);
    const int Jc   = (J < NB) ? J : (NB - 1);

    // Reads are clamped/in-bounds even for inactive halves (values discarded).
    const float* scsr = scs + half * NR;
    float inv1 = rsqrtf(scsr[Jc] + scsr[Jc + 1] + scsr[NR + Jc] + scsr[NR + Jc + 1]
                        + 1e-10f);

    const float* cell = sh + half * (NR * 9) + (g >> 1) * (NR * 9) + (Jc + (g & 1)) * 9;
    float v[9];
    float ss = 0.f;
    #pragma unroll
    for (int k = 0; k < 9; k++) {
        float f = fminf(cell[k] * inv1, 0.2f);
        v[k] = f;
        ss = fmaf(f, f, ss);
    }
    ss += __shfl_xor_sync(0xffffffffu, ss, 1);
    ss += __shfl_xor_sync(0xffffffffu, ss, 2);
    float inv2 = rsqrtf(ss + 1e-10f);

    if (half < nbr && J < NB) {
        float* dst = vbuf + half * (NB * VSTRIDE) + J * VSTRIDE + g * 9;
        #pragma unroll
        for (int k = 0; k < 9; k++) dst[k] = v[k] * inv2;
    }
    __syncthreads();

    // Coalesced copy vbuf -> out (both rows; strip the padding).
    float* obase = out + ((size_t)b * NB + I0) * (NB * 36);
    const int total = nbr * (NB * 36);
    for (int e = tid; e < total; e += K2T) {
        int row = e / (NB * 36);
        int e2  = e - row * (NB * 36);
        int Jx  = e2 / 36;
        int r   = e2 - Jx * 36;
        obase[e] = vbuf[row * (NB * VSTRIDE) + Jx * VSTRIDE + r];
    }
}

// ---------------------------------------------------------------------------
extern "C" void kernel_launch(void* const* d_in, const int* in_sizes, int n_in,
                              void* d_out, int out_size)
{
    const float* x      = (const float*)d_in[0];
    const float* coeffs = (const float*)d_in[1];
    float* out          = (float*)d_out;

    float *hist, *cellss;
    cudaGetSymbolAddress((void**)&hist, g_hist);
    cudaGetSymbolAddress((void**)&cellss, g_cellss);

    dim3 g1(2, NR, B);
    hog_cells_kernel<<<g1, TW>>>(x, coeffs, hist, cellss);

    hog_blocks_kernel<<<B * NT2, K2T>>>(hist, cellss, out);
}

// round 16
// speedup vs baseline: 1.0364x; 1.0364x over previous
#include <cuda_runtime.h>
#include <cuda_bf16.h>
#include <math.h>

#define CROP 448
#define NR   56      // cells per side
#define NB   55      // blocks per side
#define B    48
#define IMG  512
#define TOP  32

#define TW   224     // kernel-1 tile width (columns per CTA)
#define SG1  232     // staged row width: TW + 8 (4 halo/pad each side)
#define NQ   58      // staged float4 quads per row

// Cell histogram scratch: [b][cell_r][cell_c][bin]
__device__ float g_hist[(size_t)B * NR * NR * 9];
// Per-cell sum of squares: [b][cell_r][cell_c]
__device__ float g_cellss[(size_t)B * NR * NR];

__device__ __forceinline__ float fsqrt_approx(float x) {
    float r;
    asm("sqrt.approx.f32 %0, %1;" : "=f"(r) : "f"(x));
    return r;
}
__device__ __forceinline__ float frcp_approx(float x) {
    float r;
    asm("rcp.approx.f32 %0, %1;" : "=f"(r) : "f"(x));
    return r;
}

// ---------------------------------------------------------------------------
// Kernel 1: gray -> sqrt -> gradients -> per-cell prefix histograms (+cell ss)
// grid: (2, NR, B) — two 224-column tiles per cell-row, 224-thread CTAs.
// Staging: all 9 LDG.128 hoisted & issued before any sqrt/STS (MLP ~9).
// ---------------------------------------------------------------------------
__global__ __launch_bounds__(TW) void hog_cells_kernel(
    const float* __restrict__ x, const float* __restrict__ coeffs,
    float* __restrict__ hist, float* __restrict__ cellss)
{
    __shared__ float sg[10][SG1];    // global col c at index c - c0 + 4

    const int tx = blockIdx.x;       // column tile 0..1
    const int cr = blockIdx.y;       // cell row 0..55
    const int b  = blockIdx.z;
    const int cl = threadIdx.x;      // local column 0..223
    const int c0 = tx * TW;
    const int r0 = cr * 8;

    const float c0f = coeffs[0], c1f = coeffs[1], c2f = coeffs[2];
    const float* base = x + (size_t)b * 3 * IMG * IMG;

    // ---- Staging phase 1: issue ALL loads (predicated), no dependent math.
    float4 A0[3], A1[3], A2[3];
    bool   ok[3];
    int    gc_[3], i_[3];

    #pragma unroll
    for (int it = 0; it < 3; it++) {
        int e = cl + it * TW;
        ok[it] = (e < 10 * NQ);
        int i  = e / NQ;
        int qg = e - i * NQ;
        if (i > 9) i = 9;                       // clamp garbage (predicated off)
        i_[it] = i;
        int gcol = c0 - 4 + qg * 4;             // global crop col of quad start
        gc_[it] = gcol;
        int r = r0 - 1 + i;
        if (r < 0) r = -r;                      // -1 -> 1
        if (r > CROP - 1) r = 2 * (CROP - 1) - r;
        int lcol = gcol;
        if (gcol < 0)   lcol = 0;               // tile 0, leftmost quad
        if (gcol > 444) lcol = 444;             // tile 1, rightmost quad

        const float4* p = (const float4*)(base + (size_t)(r + TOP) * IMG + TOP + lcol);
        if (ok[it]) {
            A0[it] = p[0];
            A1[it] = p[(IMG * IMG) / 4];
            A2[it] = p[(2 * IMG * IMG) / 4];
        }
    }

    // ---- Staging phase 2: gray + sqrt + STS.
    #pragma unroll
    for (int it = 0; it < 3; it++) {
        if (!ok[it]) continue;
        int i = i_[it], gcol = gc_[it];
        float4 g;
        g.x = fsqrt_approx(fmaf(c0f, A0[it].x, fmaf(c1f, A1[it].x, c2f * A2[it].x)));
        g.y = fsqrt_approx(fmaf(c0f, A0[it].y, fmaf(c1f, A1[it].y, c2f * A2[it].y)));
        g.z = fsqrt_approx(fmaf(c0f, A0[it].z, fmaf(c1f, A1[it].z, c2f * A2[it].z)));
        g.w = fsqrt_approx(fmaf(c0f, A0[it].w, fmaf(c1f, A1[it].w, c2f * A2[it].w)));

        if (gcol < 0) {
            *((float4*)&sg[i][0]) = g;          // cols 0..3 (positional garbage)
            sg[i][3] = g.y;                     // col -1 := col 1 (only idx read)
        } else if (gcol > 444) {
            sg[i][228] = g.z;                   // col 448 := col 446
        } else {
            *((float4*)&sg[i][gcol - c0 + 4]) = g;
        }
    }
    __syncthreads();

    // cot(20k degrees), k = 1..8
    const float KT[8] = { 2.7474774f,  1.1917536f,  0.57735027f,  0.17632698f,
                         -0.17632698f, -0.57735027f, -1.1917536f, -2.7474774f};
    const float INF = __int_as_float(0x7f800000);

    float vreg[10];
    #pragma unroll
    for (int i = 0; i < 10; i++) vreg[i] = sg[i][cl + 4];

    // Prefix histogram: H[k] = sum of mag over pixels with angle >= 20k.
    float H[9];
    #pragma unroll
    for (int k = 0; k < 9; k++) H[k] = 0.f;

    #pragma unroll
    for (int i = 0; i < 8; i++) {
        float gr = vreg[i + 2] - vreg[i];
        float gc = sg[i + 1][cl + 5] - sg[i + 1][cl + 3];

        float mag = fsqrt_approx(fmaf(gr, gr, gc * gc));

        // w = cot(angle) = gc/gr (period 180 => no half-plane fold).
        // gr==0 -> +inf -> bin 0, matching the reference's 180 % 180 = 0.
        float w = gc * frcp_approx(gr);
        if (gr == 0.f) w = INF;

        H[0] += mag;
        #pragma unroll
        for (int k = 0; k < 8; k++)
            if (w <= KT[k]) H[k + 1] += mag;
    }

    #pragma unroll
    for (int k = 0; k < 9; k++) {
        H[k] += __shfl_xor_sync(0xffffffffu, H[k], 1);
        H[k] += __shfl_xor_sync(0xffffffffu, H[k], 2);
        H[k] += __shfl_xor_sync(0xffffffffu, H[k], 4);
    }

    if ((cl & 7) == 0) {
        int cell = (c0 + cl) >> 3;    // 0..55
        size_t cidx = ((size_t)b * NR + cr) * NR + cell;
        float ss = 0.f;
        #pragma unroll
        for (int k = 0; k < 9; k++) {
            float hk = ((k < 8) ? (H[k] - H[k + 1]) : H[8]) * (1.0f / 64.0f);
            hist[cidx * 9 + k] = hk;
            ss += hk * hk;
        }
        cellss[cidx] = ss;
    }
}

// ---------------------------------------------------------------------------
// Kernel 2: L2-Hys block normalization. One CTA per (b, I) block-row.
// [R7 version verbatim — best measured 12.0us, frozen]
// ---------------------------------------------------------------------------
#define K2_THREADS 256
#define VSTRIDE 37          // padded per-block stride in vbuf (kills conflicts)

__global__ __launch_bounds__(K2_THREADS) void hog_blocks_kernel(
    const float* __restrict__ hist, const float* __restrict__ cellss,
    float* __restrict__ out)
{
    __shared__ float sh[2 * NR * 9];      // hist rows I, I+1 (1008)
    __shared__ float scs[2 * NR];         // cell ss rows I, I+1 (112)
    __shared__ float vbuf[NB * VSTRIDE];  // normalized blocks, padded stride

    const int b = blockIdx.x / NB;
    const int I = blockIdx.x % NB;
    const int tid = threadIdx.x;

    {
        const float4* src4 = (const float4*)(hist + ((size_t)b * NR + I) * NR * 9);
        if (tid < 252) ((float4*)sh)[tid] = src4[tid];
        const float* cs = cellss + ((size_t)b * NR + I) * NR;
        if (tid < 2 * NR) scs[tid] = cs[tid];
    }
    __syncthreads();

    const int w    = tid >> 5;
    const int lane = tid & 31;
    const int g    = lane & 3;            // cell within block
    const int J    = w + 8 * (lane >> 2); // block column (may be >= NB)
    const int Jc   = (J < NB) ? J : (NB - 1);  // clamped for safe reads

    float inv1 = rsqrtf(scs[Jc] + scs[Jc + 1] + scs[NR + Jc] + scs[NR + Jc + 1]
                        + 1e-10f);

    const float* cell = sh + (g >> 1) * (NR * 9) + (Jc + (g & 1)) * 9;
    float v[9];
    float ss = 0.f;
    #pragma unroll
    for (int k = 0; k < 9; k++) {
        float f = fminf(cell[k] * inv1, 0.2f);
        v[k] = f;
        ss = fmaf(f, f, ss);
    }
    ss += __shfl_xor_sync(0xffffffffu, ss, 1);
    ss += __shfl_xor_sync(0xffffffffu, ss, 2);
    float inv2 = rsqrtf(ss + 1e-10f);

    if (J < NB) {
        float* dst = vbuf + J * VSTRIDE + g * 9;
        #pragma unroll
        for (int k = 0; k < 9; k++) dst[k] = v[k] * inv2;
    }
    __syncthreads();

    float* obase = out + (size_t)blockIdx.x * (NB * 36);
    #pragma unroll
    for (int e = tid; e < NB * 36; e += K2_THREADS) {
        int Jx = e / 36;
        int r  = e - Jx * 36;
        obase[e] = vbuf[Jx * VSTRIDE + r];
    }
}

// ---------------------------------------------------------------------------
extern "C" void kernel_launch(void* const* d_in, const int* in_sizes, int n_in,
                              void* d_out, int out_size)
{
    const float* x      = (const float*)d_in[0];
    const float* coeffs = (const float*)d_in[1];
    float* out          = (float*)d_out;

    float *hist, *cellss;
    cudaGetSymbolAddress((void**)&hist, g_hist);
    cudaGetSymbolAddress((void**)&cellss, g_cellss);

    dim3 g1(2, NR, B);
    hog_cells_kernel<<<g1, TW>>>(x, coeffs, hist, cellss);

    hog_blocks_kernel<<<B * NB, K2_THREADS>>>(hist, cellss, out);
}

// round 17
// speedup vs baseline: 1.0407x; 1.0041x over previous
#include <cuda_runtime.h>
#include <cuda_bf16.h>
#include <math.h>

#define CROP 448
#define NR   56      // cells per side
#define NB   55      // blocks per side
#define B    48
#define IMG  512
#define TOP  32

#define TW   224     // kernel-1 tile width (columns per CTA)
#define SG1  232     // staged row width: TW + 8 (4 halo/pad each side)
#define NQ   58      // staged float4 quads per row
#define RPC  2       // cell-rows per CTA
#define NROW (RPC * 8 + 2)          // 18 staged rows
#define NQT  (NROW * NQ)            // 1044 staged quads
#define NIT  ((NQT + TW - 1) / TW)  // 5 staging iterations

// Cell histogram scratch: [b][cell_r][cell_c][bin]
__device__ float g_hist[(size_t)B * NR * NR * 9];
// Per-cell sum of squares: [b][cell_r][cell_c]
__device__ float g_cellss[(size_t)B * NR * NR];

__device__ __forceinline__ float fsqrt_approx(float x) {
    float r;
    asm("sqrt.approx.f32 %0, %1;" : "=f"(r) : "f"(x));
    return r;
}
__device__ __forceinline__ float frcp_approx(float x) {
    float r;
    asm("rcp.approx.f32 %0, %1;" : "=f"(r) : "f"(x));
    return r;
}

// ---------------------------------------------------------------------------
// Kernel 1: gray -> sqrt -> gradients -> per-cell prefix histograms (+cell ss)
// grid: (2, NR/RPC, B) — 224-column tiles, 2 cell-rows per CTA (halo 1.125x).
// Staging loads hoisted in two groups (MLP 9 / 6); incremental indexing.
// ---------------------------------------------------------------------------
__global__ __launch_bounds__(TW) void hog_cells_kernel(
    const float* __restrict__ x, const float* __restrict__ coeffs,
    float* __restrict__ hist, float* __restrict__ cellss)
{
    __shared__ float sg[NROW][SG1];  // global col c at index c - c0 + 4

    const int tx  = blockIdx.x;      // column tile 0..1
    const int crg = blockIdx.y;      // cell-row group 0..27
    const int b   = blockIdx.z;
    const int cl  = threadIdx.x;     // local column 0..223
    const int c0  = tx * TW;
    const int r0  = crg * (RPC * 8);

    const float c0f = coeffs[0], c1f = coeffs[1], c2f = coeffs[2];
    const float* base = x + (size_t)b * 3 * IMG * IMG;

    // Per-iteration staged-quad indices (incremental: one division total).
    int i_[NIT], q_[NIT];
    bool ok[NIT];
    {
        int ii = cl / NQ, qq = cl - (cl / NQ) * NQ;
        #pragma unroll
        for (int it = 0; it < NIT; it++) {
            i_[it] = ii; q_[it] = qq;
            ok[it] = (cl + it * TW) < NQT;
            ii += 3; qq += TW - 3 * NQ;           // 224 - 174 = 50
            if (qq >= NQ) { qq -= NQ; ii++; }
        }
    }

    // Group A: iterations 0..2 — issue all 9 loads, then convert+store.
    {
        float4 A0[3], A1[3], A2[3];
        #pragma unroll
        for (int it = 0; it < 3; it++) {
            int i = ok[it] ? i_[it] : 0;
            int gcol = c0 - 4 + q_[it] * 4;
            int r = r0 - 1 + i;
            if (r < 0) r = -r;
            if (r > CROP - 1) r = 2 * (CROP - 1) - r;
            int lcol = gcol;
            if (gcol < 0)   lcol = 0;
            if (gcol > 444) lcol = 444;
            const float4* p = (const float4*)(base + (size_t)(r + TOP) * IMG + TOP + lcol);
            if (ok[it]) {
                A0[it] = p[0];
                A1[it] = p[(IMG * IMG) / 4];
                A2[it] = p[(2 * IMG * IMG) / 4];
            }
        }
        #pragma unroll
        for (int it = 0; it < 3; it++) {
            if (!ok[it]) continue;
            int i = i_[it];
            int gcol = c0 - 4 + q_[it] * 4;
            float4 g;
            g.x = fsqrt_approx(fmaf(c0f, A0[it].x, fmaf(c1f, A1[it].x, c2f * A2[it].x)));
            g.y = fsqrt_approx(fmaf(c0f, A0[it].y, fmaf(c1f, A1[it].y, c2f * A2[it].y)));
            g.z = fsqrt_approx(fmaf(c0f, A0[it].z, fmaf(c1f, A1[it].z, c2f * A2[it].z)));
            g.w = fsqrt_approx(fmaf(c0f, A0[it].w, fmaf(c1f, A1[it].w, c2f * A2[it].w)));
            if (gcol < 0)        { *((float4*)&sg[i][0]) = g; sg[i][3] = g.y; }
            else if (gcol > 444) { sg[i][228] = g.z; }
            else                 { *((float4*)&sg[i][gcol - c0 + 4]) = g; }
        }
    }
    // Group B: iterations 3..4.
    {
        float4 A0[2], A1[2], A2[2];
        #pragma unroll
        for (int j = 0; j < 2; j++) {
            int it = 3 + j;
            int i = ok[it] ? i_[it] : 0;
            int gcol = c0 - 4 + q_[it] * 4;
            int r = r0 - 1 + i;
            if (r < 0) r = -r;
            if (r > CROP - 1) r = 2 * (CROP - 1) - r;
            int lcol = gcol;
            if (gcol < 0)   lcol = 0;
            if (gcol > 444) lcol = 444;
            const float4* p = (const float4*)(base + (size_t)(r + TOP) * IMG + TOP + lcol);
            if (ok[it]) {
                A0[j] = p[0];
                A1[j] = p[(IMG * IMG) / 4];
                A2[j] = p[(2 * IMG * IMG) / 4];
            }
        }
        #pragma unroll
        for (int j = 0; j < 2; j++) {
            int it = 3 + j;
            if (!ok[it]) continue;
            int i = i_[it];
            int gcol = c0 - 4 + q_[it] * 4;
            float4 g;
            g.x = fsqrt_approx(fmaf(c0f, A0[j].x, fmaf(c1f, A1[j].x, c2f * A2[j].x)));
            g.y = fsqrt_approx(fmaf(c0f, A0[j].y, fmaf(c1f, A1[j].y, c2f * A2[j].y)));
            g.z = fsqrt_approx(fmaf(c0f, A0[j].z, fmaf(c1f, A1[j].z, c2f * A2[j].z)));
            g.w = fsqrt_approx(fmaf(c0f, A0[j].w, fmaf(c1f, A1[j].w, c2f * A2[j].w)));
            if (gcol < 0)        { *((float4*)&sg[i][0]) = g; sg[i][3] = g.y; }
            else if (gcol > 444) { sg[i][228] = g.z; }
            else                 { *((float4*)&sg[i][gcol - c0 + 4]) = g; }
        }
    }
    __syncthreads();

    // cot(20k degrees), k = 1..8
    const float KT[8] = { 2.7474774f,  1.1917536f,  0.57735027f,  0.17632698f,
                         -0.17632698f, -0.57735027f, -1.1917536f, -2.7474774f};
    const float INF = __int_as_float(0x7f800000);

    #pragma unroll
    for (int sub = 0; sub < RPC; sub++) {
        float vreg[10];
        #pragma unroll
        for (int i = 0; i < 10; i++) vreg[i] = sg[8 * sub + i][cl + 4];

        float H[9];
        #pragma unroll
        for (int k = 0; k < 9; k++) H[k] = 0.f;

        #pragma unroll
        for (int i = 0; i < 8; i++) {
            float gr = vreg[i + 2] - vreg[i];
            float gc = sg[8 * sub + i + 1][cl + 5] - sg[8 * sub + i + 1][cl + 3];

            float mag = fsqrt_approx(fmaf(gr, gr, gc * gc));

            // w = cot(angle) = gc/gr (period 180 => no fold). gr==0 -> +inf
            // -> bin 0, matching the reference's 180 % 180 = 0.
            float w = gc * frcp_approx(gr);
            if (gr == 0.f) w = INF;

            H[0] += mag;
            #pragma unroll
            for (int k = 0; k < 8; k++)
                if (w <= KT[k]) H[k + 1] += mag;
        }

        #pragma unroll
        for (int k = 0; k < 9; k++) {
            H[k] += __shfl_xor_sync(0xffffffffu, H[k], 1);
            H[k] += __shfl_xor_sync(0xffffffffu, H[k], 2);
            H[k] += __shfl_xor_sync(0xffffffffu, H[k], 4);
        }

        if ((cl & 7) == 0) {
            int cell = (c0 + cl) >> 3;
            int cr = crg * RPC + sub;
            size_t cidx = ((size_t)b * NR + cr) * NR + cell;
            float ss = 0.f;
            #pragma unroll
            for (int k = 0; k < 9; k++) {
                float hk = ((k < 8) ? (H[k] - H[k + 1]) : H[8]) * (1.0f / 64.0f);
                hist[cidx * 9 + k] = hk;
                ss += hk * hk;
            }
            cellss[cidx] = ss;
        }
    }
}

// ---------------------------------------------------------------------------
// Kernel 2: L2-Hys block normalization. One CTA per (b, I) block-row.
// R7 structure + division-free copy indexing.
// ---------------------------------------------------------------------------
#define K2_THREADS 256
#define VSTRIDE 37          // padded per-block stride in vbuf

__global__ __launch_bounds__(K2_THREADS) void hog_blocks_kernel(
    const float* __restrict__ hist, const float* __restrict__ cellss,
    float* __restrict__ out)
{
    __shared__ float sh[2 * NR * 9];      // hist rows I, I+1 (1008)
    __shared__ float scs[2 * NR];         // cell ss rows I, I+1 (112)
    __shared__ float vbuf[NB * VSTRIDE];  // normalized blocks, padded stride

    const int b = blockIdx.x / NB;
    const int I = blockIdx.x % NB;
    const int tid = threadIdx.x;

    {
        const float4* src4 = (const float4*)(hist + ((size_t)b * NR + I) * NR * 9);
        if (tid < 252) ((float4*)sh)[tid] = src4[tid];
        const float* cs = cellss + ((size_t)b * NR + I) * NR;
        if (tid < 2 * NR) scs[tid] = cs[tid];
    }
    __syncthreads();

    const int w    = tid >> 5;
    const int lane = tid & 31;
    const int g    = lane & 3;            // cell within block
    const int J    = w + 8 * (lane >> 2); // block column (may be >= NB)
    const int Jc   = (J < NB) ? J : (NB - 1);  // clamped for safe reads

    float inv1 = rsqrtf(scs[Jc] + scs[Jc + 1] + scs[NR + Jc] + scs[NR + Jc + 1]
                        + 1e-10f);

    const float* cell = sh + (g >> 1) * (NR * 9) + (Jc + (g & 1)) * 9;
    float v[9];
    float ss = 0.f;
    #pragma unroll
    for (int k = 0; k < 9; k++) {
        float f = fminf(cell[k] * inv1, 0.2f);
        v[k] = f;
        ss = fmaf(f, f, ss);
    }
    ss += __shfl_xor_sync(0xffffffffu, ss, 1);
    ss += __shfl_xor_sync(0xffffffffu, ss, 2);
    float inv2 = rsqrtf(ss + 1e-10f);

    if (J < NB) {
        float* dst = vbuf + J * VSTRIDE + g * 9;
        #pragma unroll
        for (int k = 0; k < 9; k++) dst[k] = v[k] * inv2;
    }
    __syncthreads();

    // Coalesced copy vbuf -> out, division-free (256 = 7*36 + 4).
    float* obase = out + (size_t)blockIdx.x * (NB * 36);
    int Jx = tid / 36;
    int r  = tid - Jx * 36;
    for (int e = tid; e < NB * 36; e += K2_THREADS) {
        obase[e] = vbuf[Jx * VSTRIDE + r];
        Jx += 7; r += 4;
        if (r >= 36) { r -= 36; Jx++; }
    }
}

// ---------------------------------------------------------------------------
extern "C" void kernel_launch(void* const* d_in, const int* in_sizes, int n_in,
                              void* d_out, int out_size)
{
    const float* x      = (const float*)d_in[0];
    const float* coeffs = (const float*)d_in[1];
    float* out          = (float*)d_out;

    float *hist, *cellss;
    cudaGetSymbolAddress((void**)&hist, g_hist);
    cudaGetSymbolAddress((void**)&cellss, g_cellss);

    dim3 g1(2, NR / RPC, B);
    hog_cells_kernel<<<g1, TW>>>(x, coeffs, hist, cellss);

    hog_blocks_kernel<<<B * NB, K2_THREADS>>>(hist, cellss, out);
}